// round 2
// baseline (speedup 1.0000x reference)
#include <cuda_runtime.h>
#include <cuda_bf16.h>
#include <stdint.h>

// out[src[e]*F + k] += edge_attrs_flat[k*E + e]   for e in [0,E), k in [0,F)
// attr_idx arrives as int32 (JAX x64-disabled downcast of the reference's int64).
// F == 16 fast path with red.global.add.v4.f32 (4 features per atomic instr).

__global__ void zero_out_kernel(float4* __restrict__ out, int n4) {
    int i = blockIdx.x * blockDim.x + threadIdx.x;
    if (i < n4) out[i] = make_float4(0.f, 0.f, 0.f, 0.f);
}

__global__ void scatter_f16_kernel(const float* __restrict__ attr,
                                   const int* __restrict__ src_idx,
                                   float* __restrict__ out,
                                   int E) {
    int e = blockIdx.x * blockDim.x + threadIdx.x;
    if (e >= E) return;
    const int s = src_idx[e];                 // row 0 of attr_idx (2, E), int32
    float* base = out + (size_t)s * 16;
#pragma unroll
    for (int kg = 0; kg < 4; kg++) {
        // flat[(4*kg + j)*E + e]: coalesced across threads for each j
        float v0 = attr[(size_t)(4 * kg + 0) * E + e];
        float v1 = attr[(size_t)(4 * kg + 1) * E + e];
        float v2 = attr[(size_t)(4 * kg + 2) * E + e];
        float v3 = attr[(size_t)(4 * kg + 3) * E + e];
        // 16B-aligned: base is 64B-aligned (s*16 floats), +16B per kg.
        asm volatile("red.global.add.v4.f32 [%0], {%1, %2, %3, %4};"
                     :: "l"(base + 4 * kg), "f"(v0), "f"(v1), "f"(v2), "f"(v3)
                     : "memory");
    }
}

// Generic fallback for F != 16 (scalar atomics).
__global__ void scatter_generic_kernel(const float* __restrict__ attr,
                                       const int* __restrict__ src_idx,
                                       float* __restrict__ out,
                                       int E, int F) {
    int e = blockIdx.x * blockDim.x + threadIdx.x;
    if (e >= E) return;
    const int s = src_idx[e];
    for (int k = 0; k < F; k++) {
        atomicAdd(&out[(size_t)s * F + k], attr[(size_t)k * E + e]);
    }
}

extern "C" void kernel_launch(void* const* d_in, const int* in_sizes, int n_in,
                              void* d_out, int out_size) {
    const float* attr = (const float*)d_in[0];   // (E, F) float32, flat
    const int*   idx  = (const int*)d_in[1];     // (2, E) int32; row 0 = src

    const int E = in_sizes[1] / 2;
    const int F = in_sizes[0] / E;
    float* out = (float*)d_out;

    // Zero-init output (poisoned to 0xAA by the harness).
    {
        int n4 = out_size / 4;
        int blocks = (n4 + 255) / 256;
        zero_out_kernel<<<blocks, 256>>>((float4*)out, n4);
    }

    int blocks = (E + 255) / 256;
    if (F == 16) {
        scatter_f16_kernel<<<blocks, 256>>>(attr, idx, out, E);
    } else {
        scatter_generic_kernel<<<blocks, 256>>>(attr, idx, out, E, F);
    }
}

// round 3
// speedup vs baseline: 1.8389x; 1.8389x over previous
#include <cuda_runtime.h>
#include <cuda_bf16.h>
#include <stdint.h>

// out[src[e]*16 + k] += attr_flat[k*E + e]
// Round-3: smem-staged transpose so RED addresses are warp-coalesced.
// 4 lanes cooperate on one edge (one 64B output row) -> 8 wavefronts per
// warp-RED instead of 32.

#define TILE 256

__global__ void zero_out_kernel(float4* __restrict__ out, int n4) {
    int i = blockIdx.x * blockDim.x + threadIdx.x;
    if (i < n4) out[i] = make_float4(0.f, 0.f, 0.f, 0.f);
}

__global__ __launch_bounds__(TILE) void scatter_f16_kernel(
        const float* __restrict__ attr,
        const int* __restrict__ src_idx,
        float* __restrict__ out,
        int E) {
    // Edge-major staging: row stride 20 floats (80B, 16B-aligned) to keep
    // STS.128 / LDS.128 (nearly) bank-conflict-free.
    __shared__ float vals[TILE][20];
    __shared__ int   sidx[TILE];

    const int t = threadIdx.x;
    const int base = blockIdx.x * TILE;
    const int e = base + t;

    // ---- Load phase: coalesced feature-major reads (1 wavefront per LDG) ----
    if (e < E) {
        sidx[t] = src_idx[e];
        float v[16];
#pragma unroll
        for (int k = 0; k < 16; k++)
            v[k] = attr[(size_t)k * E + e];
#pragma unroll
        for (int kg = 0; kg < 4; kg++) {
            float4 p = make_float4(v[4*kg+0], v[4*kg+1], v[4*kg+2], v[4*kg+3]);
            *reinterpret_cast<float4*>(&vals[t][4*kg]) = p;
        }
    }
    __syncthreads();

    // ---- Scatter phase: lane l -> edge (l/4), feature-group (l%4) ----
    // Within a warp: 8 consecutive edges x 4 contiguous 16B chunks each
    // = 8 x 64B contiguous regions -> ~8 RED wavefronts per warp-op.
    const int kg = t & 3;
    const int eg = t >> 2;           // 0..63
#pragma unroll
    for (int q = 0; q < 4; q++) {
        const int el = eg + 64 * q;  // 0..255
        if (base + el < E) {
            const int s = sidx[el];                          // 4-lane broadcast
            float4 p = *reinterpret_cast<const float4*>(&vals[el][4*kg]);
            float* dst = out + (size_t)s * 16 + 4 * kg;      // 16B-aligned
            asm volatile("red.global.add.v4.f32 [%0], {%1, %2, %3, %4};"
                         :: "l"(dst), "f"(p.x), "f"(p.y), "f"(p.z), "f"(p.w)
                         : "memory");
        }
    }
}

// Generic fallback for F != 16 (scalar atomics).
__global__ void scatter_generic_kernel(const float* __restrict__ attr,
                                       const int* __restrict__ src_idx,
                                       float* __restrict__ out,
                                       int E, int F) {
    int e = blockIdx.x * blockDim.x + threadIdx.x;
    if (e >= E) return;
    const int s = src_idx[e];
    for (int k = 0; k < F; k++)
        atomicAdd(&out[(size_t)s * F + k], attr[(size_t)k * E + e]);
}

extern "C" void kernel_launch(void* const* d_in, const int* in_sizes, int n_in,
                              void* d_out, int out_size) {
    const float* attr = (const float*)d_in[0];   // (E, F) float32, flat
    const int*   idx  = (const int*)d_in[1];     // (2, E) int32; row 0 = src

    const int E = in_sizes[1] / 2;
    const int F = in_sizes[0] / E;
    float* out = (float*)d_out;

    {   // zero-init (harness poisons d_out)
        int n4 = out_size / 4;
        zero_out_kernel<<<(n4 + 255) / 256, 256>>>((float4*)out, n4);
    }

    if (F == 16) {
        int blocks = (E + TILE - 1) / TILE;
        scatter_f16_kernel<<<blocks, TILE>>>(attr, idx, out, E);
    } else {
        int blocks = (E + 255) / 256;
        scatter_generic_kernel<<<blocks, 256>>>(attr, idx, out, E, F);
    }
}

// round 6
// speedup vs baseline: 1.8425x; 1.0019x over previous
#include <cuda_runtime.h>
#include <cuda_bf16.h>
#include <stdint.h>

// out[src[e]*16 + k] += attr_flat[k*E + e]
// Round-5: cp.async gmem->smem feature-major tile, stride 260 (16B-aligned
// rows) + chunk swizzle (el ^ 8 for planes 8..15) -> conflict-free LDS in the
// scatter; warp-coalesced red.global.add.v4.f32 unchanged.

#define TILE 256
#define VSTRIDE 260   // multiple of 4 floats: 16B-aligned rows for cp.async

__global__ void zero_out_kernel(float4* __restrict__ out, int n4) {
    int i = blockIdx.x * blockDim.x + threadIdx.x;
    if (i < n4) out[i] = make_float4(0.f, 0.f, 0.f, 0.f);
}

__device__ __forceinline__ uint32_t smem_u32(const void* p) {
    return (uint32_t)__cvta_generic_to_shared(p);
}

// chunk swizzle: planes 8..15 have their edge index XORed with 8
__device__ __forceinline__ int swz(int k, int el) {
    return el ^ (((k >> 3) & 1) << 3);
}

__global__ __launch_bounds__(TILE) void scatter_f16_kernel(
        const float* __restrict__ attr,
        const int* __restrict__ src_idx,
        float* __restrict__ out,
        int E) {
    __shared__ __align__(16) float vals[16][VSTRIDE]; // feature-major
    __shared__ int sidx[TILE];

    const int t = threadIdx.x;
    const int base = blockIdx.x * TILE;

    // ---- Async fill: 1024 x 16B chunks (16 planes x 64 quads) ----
#pragma unroll
    for (int i = 0; i < 4; i++) {
        const int c  = t + TILE * i;
        const int k  = c >> 6;
        const int q4 = (c & 63) * 4;          // edge offset of this chunk
        const int s4 = swz(k, q4);            // swizzled smem position
        const float* gsrc = attr + (size_t)k * E + base + q4;
        uint32_t sdst = smem_u32(&vals[k][s4]);
        if (base + q4 + 3 < E) {
            asm volatile("cp.async.cg.shared.global [%0], [%1], 16;"
                         :: "r"(sdst), "l"(gsrc));
        } else {
            for (int j = 0; j < 4; j++)
                vals[k][s4 + j] = (base + q4 + j < E)
                                    ? attr[(size_t)k * E + base + q4 + j] : 0.f;
        }
    }
    if (base + t < E) sidx[t] = src_idx[base + t];
    asm volatile("cp.async.commit_group;");
    asm volatile("cp.async.wait_group 0;");
    __syncthreads();

    // ---- Scatter: lane l -> edge (l/4), feature-group (l%4) ----
    // Warp covers 8 consecutive edges x 4 contiguous 16B chunks = 8 x 64B
    // contiguous regions per RED warp-op.
    const int kg = t & 3;
    const int eg = t >> 2;               // 0..63
#pragma unroll
    for (int q = 0; q < 4; q++) {
        const int el = eg + 64 * q;      // 0..255
        if (base + el < E) {
            const int s = sidx[el];
            // banks: (4k + swz) mod 32 -> octets {0-7},{16-23},{8-15},{24-31}
            float v0 = vals[4 * kg + 0][swz(4 * kg + 0, el)];
            float v1 = vals[4 * kg + 1][swz(4 * kg + 1, el)];
            float v2 = vals[4 * kg + 2][swz(4 * kg + 2, el)];
            float v3 = vals[4 * kg + 3][swz(4 * kg + 3, el)];
            float* dst = out + (size_t)s * 16 + 4 * kg;   // 16B-aligned
            asm volatile("red.global.add.v4.f32 [%0], {%1, %2, %3, %4};"
                         :: "l"(dst), "f"(v0), "f"(v1), "f"(v2), "f"(v3)
                         : "memory");
        }
    }
}

// Generic fallback for F != 16 (scalar atomics).
__global__ void scatter_generic_kernel(const float* __restrict__ attr,
                                       const int* __restrict__ src_idx,
                                       float* __restrict__ out,
                                       int E, int F) {
    int e = blockIdx.x * blockDim.x + threadIdx.x;
    if (e >= E) return;
    const int s = src_idx[e];
    for (int k = 0; k < F; k++)
        atomicAdd(&out[(size_t)s * F + k], attr[(size_t)k * E + e]);
}

extern "C" void kernel_launch(void* const* d_in, const int* in_sizes, int n_in,
                              void* d_out, int out_size) {
    const float* attr = (const float*)d_in[0];   // (E, F) float32, flat
    const int*   idx  = (const int*)d_in[1];     // (2, E) int32; row 0 = src

    const int E = in_sizes[1] / 2;
    const int F = in_sizes[0] / E;
    float* out = (float*)d_out;

    {   // zero-init (harness poisons d_out)
        int n4 = out_size / 4;
        zero_out_kernel<<<(n4 + 255) / 256, 256>>>((float4*)out, n4);
    }

    if (F == 16) {
        int blocks = (E + TILE - 1) / TILE;
        scatter_f16_kernel<<<blocks, TILE>>>(attr, idx, out, E);
    } else {
        int blocks = (E + 255) / 256;
        scatter_generic_kernel<<<blocks, 256>>>(attr, idx, out, E, F);
    }
}